// round 16
// baseline (speedup 1.0000x reference)
#include <cuda_runtime.h>
#include <cstdint>

#define D_DIM 4096
#define K_SEL 2048
#define NT    128
#define NWARP 4
#define NIT   32          // 32 x float4 per lane per pass
#define FULL  0xFFFFFFFFu
#define CAP   64
#define MAXIT 6
#define NEG_INF __int_as_float(0xff800000)
#define INV_DENS 0.000611995f   // 1 / (4096 * phi(0)) = 1/1634

// monotone float <-> uint order keys
__device__ __forceinline__ unsigned fkey(float v) {
    unsigned u = __float_as_uint(v);
    return (u & 0x80000000u) ? ~u : (u | 0x80000000u);
}
__device__ __forceinline__ float funkey(unsigned k) {
    unsigned u = (k & 0x80000000u) ? (k & 0x7FFFFFFFu) : ~k;
    return __uint_as_float(u);
}

// warp-local: exact rank jrank (1-based from top) among m (<=64) values in buf;
// returns the selected value to all lanes. Runs in the row-owning warp only.
__device__ __forceinline__ float rank64_warp(const float* buf, int m, int jrank,
                                             int lane) {
    float g0 = (lane      < m) ? buf[lane]      : NEG_INF;
    float g1 = (lane + 32 < m) ? buf[lane + 32] : NEG_INF;
    int gt0 = 0, eq0 = 0, gt1 = 0, eq1 = 0;
#pragma unroll
    for (int d = 0; d < 32; d++) {
        float o0 = __shfl_sync(FULL, g0, d);
        float o1 = __shfl_sync(FULL, g1, d);
        gt0 += (o0 > g0) + (o1 > g0);
        eq0 += (o0 == g0) + (o1 == g0);   // eq includes self
        gt1 += (o0 > g1) + (o1 > g1);
        eq1 += (o0 == g1) + (o1 == g1);
    }
    unsigned key = 0;
    if (lane      < m && gt0 < jrank && gt0 + eq0 >= jrank) key = fkey(g0);
    if (lane + 32 < m && gt1 < jrank && gt1 + eq1 >= jrank) {
        unsigned k1 = fkey(g1);
        if (k1 > key) key = k1;
    }
    key = __reduce_max_sync(FULL, key);
    return funkey(key);
}

__global__ __launch_bounds__(NT)
void topk_mask_kernel(const float* __restrict__ x, float* __restrict__ out) {
    // warp-private scratch: no block-wide synchronization anywhere
    __shared__ float gbuf[NWARP][CAP];
    __shared__ int   s_m[NWARP][MAXIT];

    const int lane = threadIdx.x & 31;
    const int wid  = threadIdx.x >> 5;
    const size_t row = (size_t)blockIdx.x * NWARP + wid;

    const float4* xin  = reinterpret_cast<const float4*>(x   + row * D_DIM);
    float4*       xout = reinterpret_cast<float4*>      (out + row * D_DIM);

    if (lane < MAXIT) s_m[wid][lane] = 0;
    __syncwarp();

    // ---- Pass A: count negatives via sign bit (streams row, fills L2) ----
    int negs = 0;
#pragma unroll 4
    for (int i = 0; i < NIT; i++) {
        float4 v = __ldcg(xin + i * 32 + lane);
        negs += (int)(__float_as_uint(v.x) >> 31);
        negs += (int)(__float_as_uint(v.y) >> 31);
        negs += (int)(__float_as_uint(v.z) >> 31);
        negs += (int)(__float_as_uint(v.w) >> 31);
    }
    const int c0 = D_DIM - __reduce_add_sync(FULL, negs);

    // ---- initial bracket + density-model window guess (R14 verbatim) ----
    float lo, hi; int clo, chiv;
    float jf, dirv;
    if (c0 >= K_SEL) {
        lo = 0.0f;  clo = c0;    hi = 8.0f; chiv = 0;
        jf = (float)(c0 - K_SEL); dirv = 1.0f;
    } else {
        lo = -8.0f; clo = D_DIM; hi = 0.0f; chiv = c0;
        jf = (float)(K_SEL - c0); dirv = -1.0f;
    }
    float tc = dirv * jf * INV_DENS;
    float dl = fmaf(jf, 0.08f, 14.0f) * INV_DENS;
    float ta = tc - dl, tb = tc + dl;

    float tf;
    int solved = 0;
#pragma unroll 1
    for (int it = 0; it < MAXIT; it++) {
        ta = fmaxf(ta, lo); tb = fminf(tb, hi);
        if (!(ta < tb)) { ta = lo; tb = hi; }

        // ---- capture pass: stream row from L2; exact counts + pushes ----
        int cb = 0, mc = 0;
#pragma unroll 4
        for (int i = 0; i < NIT; i++) {
            float4 v = __ldcg(xin + i * 32 + lane);
#pragma unroll
            for (int e = 0; e < 4; e++) {
                float u = (e == 0) ? v.x : (e == 1) ? v.y : (e == 2) ? v.z : v.w;
                bool pb = (u >= tb);
                cb += pb;
                if ((u >= ta) && !pb) {
                    mc++;
                    int p = atomicAdd(&s_m[wid][it], 1);
                    if (p < CAP) gbuf[wid][p] = u;
                }
            }
        }
        const int CB = __reduce_add_sync(FULL, cb);   // exact count(>= tb)
        const int M  = __reduce_add_sync(FULL, mc);   // exact count in [ta, tb)
        __syncwarp();                                 // pushes visible to warp

        if (CB < K_SEL && K_SEL <= CB + M && M <= CAP) {
            tf = rank64_warp(gbuf[wid], M, K_SEL - CB, lane);
            solved = 1;
            break;
        }

        // ---- guess missed (rare): shrink bracket with the exact counts ----
        const int CA = CB + M;
        if (CB >= K_SEL)      { lo = tb; clo = CB; }
        else if (CA < K_SEL)  { hi = ta; chiv = CA; }
        else                  { lo = ta; clo = CA; hi = tb; chiv = CB; } // overflow
        float span = hi - lo;
        float live = fmaxf((float)(clo - chiv), 1.0f);
        float fr   = ((float)(clo - K_SEL) + 0.5f) / live;
        tc = fmaf(fr, span, lo);
        dl = (span / live) * 20.0f;
        ta = tc - dl; tb = tc + dl;
    }
    if (!solved) tf = lo;              // warp-uniform safety net (ties collapse)

    // ---- mask pass: stream row from L2, streaming stores out ----
#pragma unroll 4
    for (int i = 0; i < NIT; i++) {
        float4 v = __ldcg(xin + i * 32 + lane);
        float4 w;
        w.x = (v.x >= tf) ? v.x : 0.0f;
        w.y = (v.y >= tf) ? v.y : 0.0f;
        w.z = (v.z >= tf) ? v.z : 0.0f;
        w.w = (v.w >= tf) ? v.w : 0.0f;
        __stcs(xout + i * 32 + lane, w);
    }
}

extern "C" void kernel_launch(void* const* d_in, const int* in_sizes, int n_in,
                              void* d_out, int out_size) {
    const float* x = (const float*)d_in[0];
    float* out = (float*)d_out;
    int rows = in_sizes[0] / D_DIM;       // 16384 for (4, 4096, 4096)
    topk_mask_kernel<<<rows / NWARP, NT>>>(x, out);
}

// round 17
// speedup vs baseline: 1.8671x; 1.8671x over previous
#include <cuda_runtime.h>
#include <cstdint>

#define D_DIM 4096
#define K_SEL 2048
#define NT    128
#define NR4   4           // float4 chunks kept in registers (16 elems)
#define NS4   4           // float4 chunks re-streamed via L1/L2 (16 elems)
#define FULL  0xFFFFFFFFu
#define CAP   64
#define MAXIT 6
#define NEG_INF __int_as_float(0xff800000)
#define INV_DENS 0.000611995f   // 1 / (4096 * phi(0)) = 1/1634

// warp 0 only: exact rank jrank (1-based from top) among m (<=64) values in buf
__device__ __forceinline__ void rank64(const float* buf, int m, int jrank,
                                       int lane, float* s_T) {
    float g0 = (lane      < m) ? buf[lane]      : NEG_INF;
    float g1 = (lane + 32 < m) ? buf[lane + 32] : NEG_INF;
    int gt0 = 0, eq0 = 0, gt1 = 0, eq1 = 0;
#pragma unroll
    for (int d = 0; d < 32; d++) {
        float o0 = __shfl_sync(FULL, g0, d);
        float o1 = __shfl_sync(FULL, g1, d);
        gt0 += (o0 > g0) + (o1 > g0);
        eq0 += (o0 == g0) + (o1 == g0);   // eq includes self
        gt1 += (o0 > g1) + (o1 > g1);
        eq1 += (o0 == g1) + (o1 == g1);
    }
    if (lane      < m && gt0 < jrank && gt0 + eq0 >= jrank) *s_T = g0;
    if (lane + 32 < m && gt1 < jrank && gt1 + eq1 >= jrank) *s_T = g1;
}

__device__ __forceinline__ int sign4(float4 v) {
    return (int)(__float_as_uint(v.x) >> 31) + (int)(__float_as_uint(v.y) >> 31)
         + (int)(__float_as_uint(v.z) >> 31) + (int)(__float_as_uint(v.w) >> 31);
}

__global__ __launch_bounds__(NT, 16)
void topk_mask_kernel(const float* __restrict__ x, float* __restrict__ out) {
    __shared__ int   s_c0;
    __shared__ int   s_cb[MAXIT];
    __shared__ int   s_mm[MAXIT];
    __shared__ float gbuf[CAP];
    __shared__ float s_T;

    const int tid  = threadIdx.x;
    const int lane = tid & 31;
    const size_t base = (size_t)blockIdx.x * D_DIM;

    const float4* xin  = reinterpret_cast<const float4*>(x   + base);
    float4*       xout = reinterpret_cast<float4*>      (out + base);

    // ---- register half: 4 LDG.128, read-once (streaming policy) ----
    float4 v4[NR4];
#pragma unroll
    for (int i = 0; i < NR4; i++) v4[i] = __ldcs(xin + i * NT + tid);

    if (tid < MAXIT) { s_cb[tid] = 0; s_mm[tid] = 0; }
    if (tid == MAXIT) s_c0 = 0;
    __syncthreads();

    // ---- Pass A: sign-bit count over both halves ----
    // streamed half uses plain ldg (first touch warms L1/L2 for the re-reads)
    int negs = 0;
#pragma unroll
    for (int i = 0; i < NR4; i++) negs += sign4(v4[i]);
#pragma unroll 2
    for (int i = 0; i < NS4; i++) {
        float4 s = __ldg(xin + (NR4 + i) * NT + tid);
        negs += sign4(s);
    }
    negs = __reduce_add_sync(FULL, negs);
    if (lane == 0) atomicAdd(&s_c0, negs);
    __syncthreads();
    const int c0 = D_DIM - s_c0;

    // ---- initial bracket + density-model window guess ----
    float lo, hi; int clo, chiv;
    float jf, dirv;
    if (c0 >= K_SEL) {
        lo = 0.0f;  clo = c0;    hi = 8.0f; chiv = 0;
        jf = (float)(c0 - K_SEL); dirv = 1.0f;
    } else {
        lo = -8.0f; clo = D_DIM; hi = 0.0f; chiv = c0;
        jf = (float)(K_SEL - c0); dirv = -1.0f;
    }
    float tc = dirv * jf * INV_DENS;
    float dl = fmaf(jf, 0.08f, 14.0f) * INV_DENS;
    float ta = tc - dl, tb = tc + dl;

    int solved = 0;
#pragma unroll 1
    for (int it = 0; it < MAXIT; it++) {
        ta = fmaxf(ta, lo); tb = fminf(tb, hi);
        if (!(ta < tb)) { ta = lo; tb = hi; }

        // ---- capture pass: regs half + L1-resident re-read half ----
        int cb = 0;
#pragma unroll
        for (int i = 0; i < NR4; i++) {
#pragma unroll
            for (int e = 0; e < 4; e++) {
                float v = (e == 0) ? v4[i].x : (e == 1) ? v4[i].y
                        : (e == 2) ? v4[i].z : v4[i].w;
                bool pb = (v >= tb);
                cb += pb;
                if ((v >= ta) && !pb) {
                    int p = atomicAdd(&s_mm[it], 1);
                    if (p < CAP) gbuf[p] = v;
                }
            }
        }
#pragma unroll 2
        for (int i = 0; i < NS4; i++) {
            float4 s = __ldg(xin + (NR4 + i) * NT + tid);
#pragma unroll
            for (int e = 0; e < 4; e++) {
                float v = (e == 0) ? s.x : (e == 1) ? s.y
                        : (e == 2) ? s.z : s.w;
                bool pb = (v >= tb);
                cb += pb;
                if ((v >= ta) && !pb) {
                    int p = atomicAdd(&s_mm[it], 1);
                    if (p < CAP) gbuf[p] = v;
                }
            }
        }
        cb = __reduce_add_sync(FULL, cb);
        if (lane == 0) atomicAdd(&s_cb[it], cb);
        __syncthreads();

        const int CB = s_cb[it];          // exact count(>= tb)
        const int M  = s_mm[it];          // exact count in [ta, tb)
        if (CB < K_SEL && K_SEL <= CB + M && M <= CAP) {
            if (tid < 32) rank64(gbuf, M, K_SEL - CB, lane, &s_T);
            __syncthreads();
            solved = 1;
            break;
        }

        // ---- guess missed (rare): shrink bracket with the exact counts ----
        const int CA = CB + M;
        if (CB >= K_SEL)      { lo = tb; clo = CB; }
        else if (CA < K_SEL)  { hi = ta; chiv = CA; }
        else                  { lo = ta; clo = CA; hi = tb; chiv = CB; } // overflow
        float span = hi - lo;
        float live = fmaxf((float)(clo - chiv), 1.0f);
        float fr   = ((float)(clo - K_SEL) + 0.5f) / live;
        tc = fmaf(fr, span, lo);
        dl = (span / live) * 20.0f;
        ta = tc - dl; tb = tc + dl;
    }

    if (!solved) {                        // never in practice: safety net
        if (tid == 0) s_T = lo;
        __syncthreads();
    }
    const float tf = s_T;

    // ---- mask + store: regs half from registers, other half from L1 ----
#pragma unroll
    for (int i = 0; i < NR4; i++) {
        float4 w;
        w.x = (v4[i].x >= tf) ? v4[i].x : 0.0f;
        w.y = (v4[i].y >= tf) ? v4[i].y : 0.0f;
        w.z = (v4[i].z >= tf) ? v4[i].z : 0.0f;
        w.w = (v4[i].w >= tf) ? v4[i].w : 0.0f;
        __stcs(xout + i * NT + tid, w);
    }
#pragma unroll 2
    for (int i = 0; i < NS4; i++) {
        float4 s = __ldg(xin + (NR4 + i) * NT + tid);
        float4 w;
        w.x = (s.x >= tf) ? s.x : 0.0f;
        w.y = (s.y >= tf) ? s.y : 0.0f;
        w.z = (s.z >= tf) ? s.z : 0.0f;
        w.w = (s.w >= tf) ? s.w : 0.0f;
        __stcs(xout + (NR4 + i) * NT + tid, w);
    }
}

extern "C" void kernel_launch(void* const* d_in, const int* in_sizes, int n_in,
                              void* d_out, int out_size) {
    const float* x = (const float*)d_in[0];
    float* out = (float*)d_out;
    int rows = in_sizes[0] / D_DIM;       // 16384 for (4, 4096, 4096)
    topk_mask_kernel<<<rows, NT>>>(x, out);
}